// round 2
// baseline (speedup 1.0000x reference)
#include <cuda_runtime.h>
#include <cuda_bf16.h>
#include <cstdint>

#define BB 32
#define TT 2048
#define VV 128
#define LL 256
#define SS 513           // 2*L+1
#define NEGF (-1e30f)

// Scratch: normalized, penalty-adjusted log-probs [B][T][V]  (~33.5 MB)
// 16-byte aligned: accessed via float4.
__device__ __align__(16) float g_lp[(size_t)BB * TT * VV];
__device__ float g_loss[BB];

__device__ __forceinline__ float penalty_of(int v) {
    if (v == 0 || v == 3) return 1.0f;                                // blank, space
    if (v == 11 || v == 15 || v == 19 || v == 25 || v == 31) return 5.0f; // vowels
    return 0.0f;
}

// ---------------------------------------------------------------------------
// Pass 1: lp[b,t,v] = (x - pen)[v] - logsumexp_v(x - pen)
// One warp per (b,t) row; each lane owns 4 consecutive vocab entries (float4).
// ---------------------------------------------------------------------------
__global__ void lp_kernel(const float* __restrict__ y_pred) {
    int gwarp = (blockIdx.x * blockDim.x + threadIdx.x) >> 5;
    int lane  = threadIdx.x & 31;
    if (gwarp >= BB * TT) return;

    const float4* row = reinterpret_cast<const float4*>(y_pred + (size_t)gwarp * VV);
    float4 x = row[lane];
    int v0 = lane * 4;
    x.x -= penalty_of(v0 + 0);
    x.y -= penalty_of(v0 + 1);
    x.z -= penalty_of(v0 + 2);
    x.w -= penalty_of(v0 + 3);

    float m = fmaxf(fmaxf(x.x, x.y), fmaxf(x.z, x.w));
    #pragma unroll
    for (int o = 16; o > 0; o >>= 1)
        m = fmaxf(m, __shfl_xor_sync(0xffffffffu, m, o));

    float s = __expf(x.x - m) + __expf(x.y - m) + __expf(x.z - m) + __expf(x.w - m);
    #pragma unroll
    for (int o = 16; o > 0; o >>= 1)
        s += __shfl_xor_sync(0xffffffffu, s, o);

    float lse = m + __logf(s);
    float4 out;
    out.x = x.x - lse; out.y = x.y - lse; out.z = x.z - lse; out.w = x.w - lse;
    reinterpret_cast<float4*>(g_lp + (size_t)gwarp * VV)[lane] = out;
}

// ---------------------------------------------------------------------------
// Pass 2: CTC forward. One CTA per batch element. 544 threads:
//   thread s (< 513) owns state s; warp 0 additionally streams lp rows.
// Double-buffered alpha + row, one __syncthreads per time step.
// ---------------------------------------------------------------------------
__global__ void __launch_bounds__(544, 1) ctc_kernel(const int* __restrict__ y_true) {
    __shared__ __align__(16) float sh_alpha[2][SS];
    __shared__ __align__(16) float sh_row[2][VV];
    __shared__ int   sh_lab[LL];
    __shared__ int   sh_len;

    const int b   = blockIdx.x;
    const int tid = threadIdx.x;
    const int s   = tid;

    if (tid < LL) sh_lab[tid] = y_true[b * LL + tid];
    if (tid == 0) sh_len = 0;
    __syncthreads();
    if (tid < LL && sh_lab[tid] != 0) atomicAdd(&sh_len, 1);

    // Per-thread state config (labels are ready; len finalized later).
    __syncthreads();
    int  myext  = 0;      // extended label index for state s (blank = 0)
    bool myskip = false;  // s-2 -> s transition allowed
    if (s < SS) {
        if (s & 1) {
            myext = sh_lab[(s - 1) >> 1];
            if (s >= 3) {
                int prev = sh_lab[(s - 3) >> 1];
                myskip = (myext != 0) && (myext != prev);
            }
        }
    }

    const float* lp_b = g_lp + (size_t)b * TT * VV;

    // Load row 0 (for alpha init) and prefetch row 1 into registers.
    float4 rnext;
    if (tid < 32) {
        reinterpret_cast<float4*>(sh_row[0])[tid] =
            reinterpret_cast<const float4*>(lp_b)[tid];
        rnext = reinterpret_cast<const float4*>(lp_b + VV)[tid];
    }
    __syncthreads();

    if (s < SS) {
        float a0 = NEGF;
        if (s == 0) a0 = sh_row[0][0];      // blank at t=0
        if (s == 1) a0 = sh_row[0][myext];  // first label at t=0
        sh_alpha[0][s] = a0;
    }

    for (int t = 1; t < TT; ++t) {
        const int cur = t & 1;
        if (tid < 32) {
            reinterpret_cast<float4*>(sh_row[cur])[tid] = rnext;   // row t -> smem
            if (t + 1 < TT)
                rnext = reinterpret_cast<const float4*>(lp_b + (size_t)(t + 1) * VV)[tid];
        }
        __syncthreads();  // alpha[t-1] visible, row t visible

        if (s < SS) {
            const float* ap = sh_alpha[cur ^ 1];
            float a  = ap[s];
            float a1 = (s >= 1)  ? ap[s - 1] : NEGF;
            float a2 = myskip    ? ap[s - 2] : NEGF;
            float m  = fmaxf(a, fmaxf(a1, a2));
            float sum = __expf(a - m) + __expf(a1 - m) + __expf(a2 - m);
            sh_alpha[cur][s] = m + __logf(sum) + sh_row[cur][myext];
        }
    }
    __syncthreads();

    if (tid == 0) {
        const float* af = sh_alpha[(TT - 1) & 1];
        int il = 2 * sh_len;            // len in [128,256] -> il in [256,512]
        int ip = il - 1;
        float aL = af[il];
        float aP = af[ip];
        float m  = fmaxf(aL, aP);
        float ll = m + __logf(__expf(aL - m) + __expf(aP - m));
        g_loss[b] = -ll;
    }
}

// ---------------------------------------------------------------------------
// Pass 3: mean over batch + 1e-7
// ---------------------------------------------------------------------------
__global__ void finalize_kernel(float* __restrict__ out) {
    int t = threadIdx.x;            // 32 threads
    float v = g_loss[t];
    #pragma unroll
    for (int o = 16; o > 0; o >>= 1)
        v += __shfl_xor_sync(0xffffffffu, v, o);
    if (t == 0) out[0] = v * (1.0f / (float)BB) + 1e-7f;
}

extern "C" void kernel_launch(void* const* d_in, const int* in_sizes, int n_in,
                              void* d_out, int out_size) {
    const float* y_pred = (const float*)d_in[0];
    const int*   y_true = (const int*)d_in[1];
    float*       out    = (float*)d_out;

    // Pass 1: 65536 rows, one warp each; 8 warps per block.
    lp_kernel<<<(BB * TT) / 8, 256>>>(y_pred);
    // Pass 2: one CTA per batch element.
    ctc_kernel<<<BB, 544>>>(y_true);
    // Pass 3: scalar reduction.
    finalize_kernel<<<1, 32>>>(out);
}

// round 5
// speedup vs baseline: 1.2047x; 1.2047x over previous
#include <cuda_runtime.h>
#include <cuda_bf16.h>
#include <cstdint>
#include <math.h>

#define BB 32
#define TT 2048
#define VV 128
#define LL 256
#define SS 513           // 2*L+1
#define NTHR 544         // 17 warps
#define NW   (NTHR / 32)
#define EDEAD (-(1 << 28))
#define LN2F 0.69314718055994531f

// Scratch: penalty-adjusted softmax probabilities [B][T][V]  (~33.5 MB)
__device__ __align__(16) float g_p[(size_t)BB * TT * VV];
__device__ float g_loss[BB];

__device__ __forceinline__ float penalty_of(int v) {
    if (v == 0 || v == 3) return 1.0f;                                // blank, space
    if (v == 11 || v == 15 || v == 19 || v == 25 || v == 31) return 5.0f; // vowels
    return 0.0f;
}

// 2^d for d <= 0, exact, flushes to 0 for d < -126  (d must be <= 0)
__device__ __forceinline__ float pow2_clamped(int d) {
    int be = 127 + d;
    be = be < 0 ? 0 : be;
    return __int_as_float((uint32_t)be << 23);
}

// ---------------------------------------------------------------------------
// Pass 1: p[b,t,v] = softmax_v(y_pred - penalty)   (linear domain)
// ---------------------------------------------------------------------------
__global__ void prob_kernel(const float* __restrict__ y_pred) {
    int gwarp = (blockIdx.x * blockDim.x + threadIdx.x) >> 5;
    int lane  = threadIdx.x & 31;
    if (gwarp >= BB * TT) return;

    const float4* row = reinterpret_cast<const float4*>(y_pred + (size_t)gwarp * VV);
    float4 x = row[lane];
    int v0 = lane * 4;
    x.x -= penalty_of(v0 + 0);
    x.y -= penalty_of(v0 + 1);
    x.z -= penalty_of(v0 + 2);
    x.w -= penalty_of(v0 + 3);

    float m = fmaxf(fmaxf(x.x, x.y), fmaxf(x.z, x.w));
    #pragma unroll
    for (int o = 16; o > 0; o >>= 1)
        m = fmaxf(m, __shfl_xor_sync(0xffffffffu, m, o));

    float s = __expf(x.x - m) + __expf(x.y - m) + __expf(x.z - m) + __expf(x.w - m);
    #pragma unroll
    for (int o = 16; o > 0; o >>= 1)
        s += __shfl_xor_sync(0xffffffffu, s, o);

    float lse = m + __logf(s);
    float4 out;
    out.x = __expf(x.x - lse);
    out.y = __expf(x.y - lse);
    out.z = __expf(x.z - lse);
    out.w = __expf(x.w - lse);
    reinterpret_cast<float4*>(g_p + (size_t)gwarp * VV)[lane] = out;
}

// ---------------------------------------------------------------------------
// Pass 2: CTC forward with per-state extended-range floats (m, e).
// One CTA per batch element; thread s owns state s. Neighbor exchange via
// shfl.up (intra-warp) + one halo state per warp boundary via smem.
// One __syncthreads per step. No MUFU in the loop.
// ---------------------------------------------------------------------------
__global__ void __launch_bounds__(NTHR, 1) ctc_kernel(const int* __restrict__ y_true) {
    __shared__ float hM[2][NW + 1];   // halo mantissa of state 32w-1
    __shared__ int   hE[2][NW + 1];   // halo exponent
    __shared__ float Fm[NTHR];
    __shared__ int   Fe[NTHR];
    __shared__ int   sh_lab[LL];
    __shared__ int   sh_len;

    const int b    = blockIdx.x;
    const int tid  = threadIdx.x;
    const int s    = tid;
    const int lane = tid & 31;
    const int wid  = tid >> 5;

    if (tid < LL) sh_lab[tid] = y_true[b * LL + tid];
    if (tid == 0) {
        sh_len = 0;
        hM[0][0] = 0.0f; hM[1][0] = 0.0f;
        hE[0][0] = EDEAD; hE[1][0] = EDEAD;
    }
    __syncthreads();
    if (tid < LL && sh_lab[tid] != 0) atomicAdd(&sh_len, 1);
    __syncthreads();

    int  myext  = 0;
    bool myskip = false;
    const bool ghost = (s >= SS);
    if (!ghost && (s & 1)) {
        myext = sh_lab[(s - 1) >> 1];
        if (s >= 3) {
            int prev = sh_lab[(s - 3) >> 1];
            myskip = (myext != 0) && (myext != prev);
        }
    }

    const float* pb = g_p + (size_t)b * TT * VV;

    // ----- t = 0 init: alpha in (m, e) form -----
    float a0 = 0.0f;
    if (s == 0) a0 = pb[0];
    if (s == 1) a0 = pb[myext];
    float m; int e;
    if (a0 > 0.0f) {
        int bits = __float_as_int(a0);
        int ea = (bits >> 23) - 127;
        e = ea;
        m = __int_as_float(bits - (ea << 23));   // in [1,2)
    } else {
        m = 0.0f; e = EDEAD;
    }
    if (lane == 31) { hM[0][wid + 1] = m; hE[0][wid + 1] = e; }

    // prefetch queue: p for my state at t=1..4 (ghosts stay 0)
    float q0 = ghost ? 0.0f : pb[(size_t)1 * VV + myext];
    float q1 = ghost ? 0.0f : pb[(size_t)2 * VV + myext];
    float q2 = ghost ? 0.0f : pb[(size_t)3 * VV + myext];
    float q3 = ghost ? 0.0f : pb[(size_t)4 * VV + myext];

    __syncthreads();

    #pragma unroll 4
    for (int t = 1; t < TT; ++t) {
        const int pbuf = (t - 1) & 1;
        const int cbuf = t & 1;
        float p = q0;
        q0 = q1; q1 = q2; q2 = q3;
        q3 = (!ghost && t + 4 < TT) ? pb[(size_t)(t + 4) * VV + myext] : 0.0f;

        // neighbors from previous step (registers of lanes s-1, s-2)
        float m1 = __shfl_up_sync(0xffffffffu, m, 1);
        int   e1 = __shfl_up_sync(0xffffffffu, e, 1);
        float m2 = __shfl_up_sync(0xffffffffu, m, 2);
        int   e2 = __shfl_up_sync(0xffffffffu, e, 2);
        if (lane == 0) { m1 = hM[pbuf][wid]; e1 = hE[pbuf][wid]; }  // s-1 across warp
        if (lane == 1) { m2 = hM[pbuf][wid]; e2 = hE[pbuf][wid]; }  // s-2 across warp
        if (!myskip) e2 = EDEAD;   // kills the s-2 term (even states & no-skip odd)

        int emax = max(e, max(e1, e2));
        float f0 = pow2_clamped(e  - emax);
        float f1 = pow2_clamped(e1 - emax);
        float f2 = pow2_clamped(e2 - emax);
        float sum  = fmaf(m, f0, fmaf(m1, f1, m2 * f2));
        float anew = sum * p;              // true value = anew * 2^emax

        // renormalize: m in [1,2), e absolute
        int bits = __float_as_int(anew);
        int eadj = (bits >> 23) - 127;
        e = emax + eadj;
        m = anew * __int_as_float((uint32_t)(127 - eadj) << 23);  // exact 2^-eadj; 0 stays 0

        if (lane == 31) { hM[cbuf][wid + 1] = m; hE[cbuf][wid + 1] = e; }
        __syncthreads();
    }

    // ----- final readout -----
    Fm[tid] = m; Fe[tid] = e;
    __syncthreads();
    if (tid == 0) {
        int il = 2 * sh_len;      // in [256, 512]
        int ip = il - 1;
        float l1 = (Fm[il] > 0.0f) ? (__logf(Fm[il]) + (float)Fe[il] * LN2F) : -3.0e38f;
        float l2 = (Fm[ip] > 0.0f) ? (__logf(Fm[ip]) + (float)Fe[ip] * LN2F) : -3.0e38f;
        float mx = fmaxf(l1, l2);
        float ll = mx + __logf(__expf(l1 - mx) + __expf(l2 - mx));
        g_loss[b] = -ll;
    }
}

// ---------------------------------------------------------------------------
// Pass 3: mean over batch + 1e-7
// ---------------------------------------------------------------------------
__global__ void finalize_kernel(float* __restrict__ out) {
    int t = threadIdx.x;
    float v = g_loss[t];
    #pragma unroll
    for (int o = 16; o > 0; o >>= 1)
        v += __shfl_xor_sync(0xffffffffu, v, o);
    if (t == 0) out[0] = v * (1.0f / (float)BB) + 1e-7f;
}

extern "C" void kernel_launch(void* const* d_in, const int* in_sizes, int n_in,
                              void* d_out, int out_size) {
    const float* y_pred = (const float*)d_in[0];
    const int*   y_true = (const int*)d_in[1];
    float*       out    = (float*)d_out;

    prob_kernel<<<(BB * TT) / 8, 256>>>(y_pred);
    ctc_kernel<<<BB, NTHR>>>(y_true);
    finalize_kernel<<<1, 32>>>(out);
}